// round 5
// baseline (speedup 1.0000x reference)
#include <cuda_runtime.h>
#include <cuda_fp16.h>
#include <stdint.h>
#include <math.h>

#define B_  64
#define N_  1024
#define D_  512
#define K_  64
#define EPS_ 1e-12f

// ---------------- scratch ----------------
__device__ __half g_wT[K_ * D_];                 // w^T fp16 [k][d]
__device__ float g_pv[2 * B_ * D_ * K_];         // v partials [h][b][d][k]
__device__ float g_asp[2 * B_ * K_];             // asum partials [h][b][k]

// ---------------- helpers ----------------
__device__ __forceinline__ uint32_t smem_u32(const void* p) {
    uint32_t a;
    asm("{ .reg .u64 t; cvta.to.shared.u64 t, %1; cvt.u32.u64 %0, t; }" : "=r"(a) : "l"(p));
    return a;
}
__device__ __forceinline__ uint32_t sw1024(uint32_t off) { return off ^ (((off >> 10) & 7) << 4); }
__device__ __forceinline__ uint32_t sw256(uint32_t off)  { return off ^ (((off >> 8) & 7) << 4); }

__device__ __forceinline__ void ldsm_x4(uint32_t* r, uint32_t a) {
    asm volatile("ldmatrix.sync.aligned.m8n8.x4.shared.b16 {%0,%1,%2,%3}, [%4];"
        : "=r"(r[0]), "=r"(r[1]), "=r"(r[2]), "=r"(r[3]) : "r"(a));
}
__device__ __forceinline__ void ldsm_x4t(uint32_t* r, uint32_t a) {
    asm volatile("ldmatrix.sync.aligned.m8n8.x4.trans.shared.b16 {%0,%1,%2,%3}, [%4];"
        : "=r"(r[0]), "=r"(r[1]), "=r"(r[2]), "=r"(r[3]) : "r"(a));
}
__device__ __forceinline__ void mma16816(float* c, const uint32_t* a, uint32_t b0, uint32_t b1) {
    asm volatile("mma.sync.aligned.m16n8k16.row.col.f32.f16.f16.f32 "
        "{%0,%1,%2,%3}, {%4,%5,%6,%7}, {%8,%9}, {%0,%1,%2,%3};"
        : "+f"(c[0]), "+f"(c[1]), "+f"(c[2]), "+f"(c[3])
        : "r"(a[0]), "r"(a[1]), "r"(a[2]), "r"(a[3]), "r"(b0), "r"(b1));
}
__device__ __forceinline__ void sts64(uint32_t addr, uint32_t a, uint32_t b) {
    asm volatile("st.shared.v2.b32 [%0], {%1,%2};" :: "r"(addr), "r"(a), "r"(b) : "memory");
}
__device__ __forceinline__ void sts128(uint32_t addr, uint4 v) {
    asm volatile("st.shared.v4.b32 [%0], {%1,%2,%3,%4};"
        :: "r"(addr), "r"(v.x), "r"(v.y), "r"(v.z), "r"(v.w) : "memory");
}
__device__ __forceinline__ void sts16(uint32_t addr, __half v) {
    uint16_t u = *(uint16_t*)&v;
    asm volatile("st.shared.b16 [%0], %1;" :: "r"(addr), "h"(u) : "memory");
}
__device__ __forceinline__ uint32_t h2(float a, float b) {
    __half2 h = __floats2half2_rn(a, b);
    return *(uint32_t*)&h;
}

// ---------------- kernel 0: w -> wT fp16 ----------------
__global__ __launch_bounds__(256) void prep_kernel(const float* __restrict__ w) {
    int e = blockIdx.x * 256 + threadIdx.x;
    int k = e >> 9, d = e & 511;
    g_wT[(size_t)k * D_ + d] = __float2half(w[(size_t)d * K_ + k]);
}

// ---------------- fused kernel: GEMM1 + softmax + GEMM2 ----------------
// grid (2, 64): blockIdx.x = n-half, blockIdx.y = batch. 256 threads.
// smem: XH x-subtile 128n x 512d fp16 (128KB, sw1024) @0
//       WS w 64k x 512d fp16 (64KB, sw1024)           @131072
//       AT a^T 64k x 128n fp16 (16KB, sw256)          @196608  (overlaid by s_red post-loop)
#define SMEM_FUSED (131072 + 65536 + 16384)

__global__ __launch_bounds__(256) void fused_kernel(const float* __restrict__ x) {
    extern __shared__ __align__(1024) char smem[];
    const uint32_t S0 = smem_u32(smem);
    const uint32_t XH = S0, WS = S0 + 131072, AT = S0 + 196608;
    float* s_red = (float*)(smem + 196608);

    const int t = threadIdx.x, wid = t >> 5, l = t & 31;
    const int h = blockIdx.x, b = blockIdx.y;

    // lane mappings (proven in R4)
    const int rA  = (l & 15);
    const int cA8 = (l >> 4) << 3;
    const int rT  = (l & 7) + ((l >> 4) << 3);
    const int c8  = ((l >> 3) & 1) << 3;
    const int q  = l >> 2, qq = l & 3;

    // load w tile (64 rows x 1024B, swizzled)
#pragma unroll
    for (int i = 0; i < 16; i++) {
        int e = t + i * 256, r = e >> 6, c16 = e & 63;
        sts128(WS + sw1024((uint32_t)(r * 1024 + c16 * 16)),
               *(const uint4*)((const char*)g_wT + (size_t)r * 1024 + c16 * 16));
    }

    float acc2[4][8][4];
#pragma unroll
    for (int m = 0; m < 4; m++)
#pragma unroll
        for (int f = 0; f < 8; f++)
#pragma unroll
            for (int j = 0; j < 4; j++) acc2[m][f][j] = 0.f;
    float asA[8], asB[8];
#pragma unroll
    for (int f = 0; f < 8; f++) { asA[f] = 0.f; asB[f] = 0.f; }

    const float* xb = x + ((size_t)b * N_ + (size_t)h * 512) * D_;
    float4 rx[8];

    auto ldg_chunk = [&](int t4, int c) {
#pragma unroll
        for (int i = 0; i < 8; i++) {
            int e = t + i * 256, r = e >> 4, f4 = e & 15;
            rx[i] = *(const float4*)(xb + (size_t)(t4 * 128 + r) * D_ + c * 64 + f4 * 4);
        }
    };
    auto sts_chunk = [&](int c) {
#pragma unroll
        for (int i = 0; i < 8; i++) {
            int e = t + i * 256, r = e >> 4, f4 = e & 15;
            sts64(XH + sw1024((uint32_t)(r * 1024 + c * 128 + f4 * 8)),
                  h2(rx[i].x, rx[i].y), h2(rx[i].z, rx[i].w));
        }
    };

    ldg_chunk(0, 0);

    for (int t4 = 0; t4 < 4; t4++) {
        sts_chunk(0);
        __syncthreads();            // covers w-load on first iteration

        float acc1[8][4];
#pragma unroll
        for (int f = 0; f < 8; f++)
#pragma unroll
            for (int j = 0; j < 4; j++) acc1[f][j] = 0.f;

        // ---- GEMM1: s(128n x 64k) over d, streamed in 8 chunks of 64 ----
#pragma unroll 1
        for (int c = 0; c < 8; c++) {
            if (c < 7)      ldg_chunk(t4, c + 1);
            else if (t4 < 3) ldg_chunk(t4 + 1, 0);
#pragma unroll
            for (int ks = 0; ks < 4; ks++) {
                const int k0d = c * 64 + ks * 16;
                uint32_t ah[4];
                ldsm_x4(ah, XH + sw1024((uint32_t)((16 * wid + rA) * 1024 + (k0d + cA8) * 2)));
#pragma unroll
                for (int fp = 0; fp < 4; fp++) {
                    uint32_t bh[4];
                    ldsm_x4(bh, WS + sw1024((uint32_t)((fp * 16 + rT) * 1024 + (k0d + c8) * 2)));
                    mma16816(acc1[2*fp],   ah, bh[0], bh[1]);
                    mma16816(acc1[2*fp+1], ah, bh[2], bh[3]);
                }
            }
            if (c < 7) {
                sts_chunk(c + 1);
                __syncthreads();
            }
        }

        // ---- softmax over k=64 (rows r0=16wid+q, r0+8; row lives in quad) ----
        float m0 = -1e30f, m1 = -1e30f;
#pragma unroll
        for (int f = 0; f < 8; f++) {
            m0 = fmaxf(m0, fmaxf(acc1[f][0], acc1[f][1]));
            m1 = fmaxf(m1, fmaxf(acc1[f][2], acc1[f][3]));
        }
        m0 = fmaxf(m0, __shfl_xor_sync(~0u, m0, 1));
        m0 = fmaxf(m0, __shfl_xor_sync(~0u, m0, 2));
        m1 = fmaxf(m1, __shfl_xor_sync(~0u, m1, 1));
        m1 = fmaxf(m1, __shfl_xor_sync(~0u, m1, 2));
        float s0 = 0.f, s1 = 0.f;
#pragma unroll
        for (int f = 0; f < 8; f++) {
            acc1[f][0] = __expf(acc1[f][0] - m0);
            acc1[f][1] = __expf(acc1[f][1] - m0);
            acc1[f][2] = __expf(acc1[f][2] - m1);
            acc1[f][3] = __expf(acc1[f][3] - m1);
            s0 += acc1[f][0] + acc1[f][1];
            s1 += acc1[f][2] + acc1[f][3];
        }
        s0 += __shfl_xor_sync(~0u, s0, 1); s0 += __shfl_xor_sync(~0u, s0, 2);
        s1 += __shfl_xor_sync(~0u, s1, 1); s1 += __shfl_xor_sync(~0u, s1, 2);
        const float i0 = 1.0f / s0, i1 = 1.0f / s1;
        const int r0 = 16 * wid + q;
#pragma unroll
        for (int f = 0; f < 8; f++) {
            const int k0 = 8 * f + 2 * qq;
            float a0 = acc1[f][0] * i0, a1 = acc1[f][1] * i0;
            float a2 = acc1[f][2] * i1, a3 = acc1[f][3] * i1;
            asA[f] += a0 + a2;   // k0
            asB[f] += a1 + a3;   // k0+1
            sts16(AT + sw256((uint32_t)(k0 * 256 + r0 * 2)),           __float2half(a0));
            sts16(AT + sw256((uint32_t)((k0 + 1) * 256 + r0 * 2)),     __float2half(a1));
            sts16(AT + sw256((uint32_t)(k0 * 256 + (r0 + 8) * 2)),     __float2half(a2));
            sts16(AT + sw256((uint32_t)((k0 + 1) * 256 + (r0 + 8) * 2)), __float2half(a3));
        }
        __syncthreads();

        // ---- GEMM2: acc2[64d x 64k per warp] += xT(this subtile) @ a ----
#pragma unroll
        for (int ks = 0; ks < 8; ks++) {
            const int nk = ks * 16;
            uint32_t ah4[4][4];
#pragma unroll
            for (int m = 0; m < 4; m++)
                ldsm_x4t(ah4[m], XH + sw1024((uint32_t)((nk + rT) * 1024 + (wid * 64 + m * 16 + c8) * 2)));
#pragma unroll
            for (int fp = 0; fp < 4; fp++) {
                uint32_t bh[4];
                ldsm_x4(bh, AT + sw256((uint32_t)((fp * 16 + rT) * 256 + (nk + c8) * 2)));
#pragma unroll
                for (int m = 0; m < 4; m++) {
                    mma16816(acc2[m][2*fp],   ah4[m], bh[0], bh[1]);
                    mma16816(acc2[m][2*fp+1], ah4[m], bh[2], bh[3]);
                }
            }
        }
        __syncthreads();   // XH/AT free for next subtile
    }

    // ---- epilogue: asum partials + v partials ----
#pragma unroll
    for (int f = 0; f < 8; f++) {
        float vA = asA[f], vB = asB[f];
        vA += __shfl_xor_sync(~0u, vA, 4);  vA += __shfl_xor_sync(~0u, vA, 8);  vA += __shfl_xor_sync(~0u, vA, 16);
        vB += __shfl_xor_sync(~0u, vB, 4);  vB += __shfl_xor_sync(~0u, vB, 8);  vB += __shfl_xor_sync(~0u, vB, 16);
        asA[f] = vA; asB[f] = vB;
    }
    if (l < 4) {
#pragma unroll
        for (int f = 0; f < 8; f++) {
            s_red[wid * 64 + 8 * f + 2 * l]     = asA[f];
            s_red[wid * 64 + 8 * f + 2 * l + 1] = asB[f];
        }
    }
    __syncthreads();
    if (t < 64) {
        float s = 0.f;
#pragma unroll
        for (int w8 = 0; w8 < 8; w8++) s += s_red[w8 * 64 + t];
        g_asp[(h * B_ + b) * 64 + t] = s;
    }

    float* pv = g_pv + ((size_t)(h * B_ + b)) * D_ * K_;
#pragma unroll
    for (int m = 0; m < 4; m++) {
        const int dg0 = wid * 64 + m * 16 + q;
#pragma unroll
        for (int f = 0; f < 8; f++) {
            const int k0 = 8 * f + 2 * qq;
            *(float2*)(pv + (size_t)dg0 * K_ + k0)       = make_float2(acc2[m][f][0], acc2[m][f][1]);
            *(float2*)(pv + (size_t)(dg0 + 8) * K_ + k0) = make_float2(acc2[m][f][2], acc2[m][f][3]);
        }
    }
}

// ---------------- scale kernel: per-batch norms + output ----------------
__global__ __launch_bounds__(256) void scale_kernel(const float* __restrict__ Cm,
                                                    float* __restrict__ out) {
    __shared__ float sAs[64], sP[256], sS[64], sInv[64];
    __shared__ float sG;
    const int b = blockIdx.x, t = threadIdx.x, k = t & 63;
    if (t < 64) sAs[t] = g_asp[b * 64 + t] + g_asp[(B_ + b) * 64 + t];
    __syncthreads();
    const float as = sAs[k];
    const float* p0 = g_pv + (size_t)b * (D_ * K_);
    const float* p1 = g_pv + (size_t)(B_ + b) * (D_ * K_);

    float S = 0.f;
#pragma unroll 8
    for (int e = t; e < D_ * K_; e += 256) {
        float v = p0[e] + p1[e] + as * Cm[e];
        S += v * v;
    }
    sP[t] = S;
    __syncthreads();
    if (t < 64) {
        float s = sP[t] + sP[t + 64] + sP[t + 128] + sP[t + 192];
        sS[t] = s;
        sInv[t] = rsqrtf(s + EPS_);
    }
    __syncthreads();
    if (t < 32) {
        float a0 = sS[t], a1 = sS[t + 32];
        float g = a0 / (a0 + EPS_) + a1 / (a1 + EPS_);
#pragma unroll
        for (int off = 16; off; off >>= 1) g += __shfl_xor_sync(~0u, g, off);
        if (t == 0) sG = rsqrtf(g + EPS_);
    }
    __syncthreads();
    const float scale = sInv[k] * sG;
    float* ob = out + (size_t)b * (D_ * K_);
#pragma unroll 8
    for (int e = t; e < D_ * K_; e += 256) {
        float v = p0[e] + p1[e] + as * Cm[e];
        ob[e] = v * scale;
    }
}

// ---------------------------------------------------------------------------
extern "C" void kernel_launch(void* const* d_in, const int* in_sizes, int n_in,
                              void* d_out, int out_size) {
    const float* x  = (const float*)d_in[0];   // [B,H,W,D]
    const float* w  = (const float*)d_in[1];   // [D,K]
    const float* Cm = (const float*)d_in[2];   // [D,K]
    float* out = (float*)d_out;                // [B, D*K]

    cudaFuncSetAttribute(fused_kernel, cudaFuncAttributeMaxDynamicSharedMemorySize, SMEM_FUSED);

    prep_kernel<<<128, 256>>>(w);
    fused_kernel<<<dim3(2, B_), 256, SMEM_FUSED>>>(x);
    scale_kernel<<<B_, 256>>>(Cm, out);
}

// round 6
// speedup vs baseline: 1.4029x; 1.4029x over previous
#include <cuda_runtime.h>
#include <cuda_fp16.h>
#include <stdint.h>
#include <math.h>

#define B_  64
#define N_  1024
#define D_  512
#define K_  64
#define EPS_ 1e-12f

// ---------------- scratch ----------------
__device__ __half g_wT[K_ * D_];                         // w^T fp16 [k][d]
__device__ __half g_aT[(size_t)B_ * K_ * N_];            // a^T fp16 [b][k][n]
__device__ float g_asum_part[B_ * 8 * K_];
__device__ float g_S_part[B_ * 8 * K_];
__device__ float g_v[(size_t)B_ * D_ * K_];              // v pre-norm [b][d][k]

// ---------------- helpers ----------------
__device__ __forceinline__ uint32_t smem_u32(const void* p) {
    uint32_t a;
    asm("{ .reg .u64 t; cvta.to.shared.u64 t, %1; cvt.u32.u64 %0, t; }" : "=r"(a) : "l"(p));
    return a;
}
__device__ __forceinline__ uint32_t sw128(uint32_t off) { return off ^ ((off >> 3) & 0x70); }

__device__ __forceinline__ void ldsm_x4(uint32_t* r, uint32_t a) {
    asm volatile("ldmatrix.sync.aligned.m8n8.x4.shared.b16 {%0,%1,%2,%3}, [%4];"
        : "=r"(r[0]), "=r"(r[1]), "=r"(r[2]), "=r"(r[3]) : "r"(a));
}
__device__ __forceinline__ void ldsm_x4t(uint32_t* r, uint32_t a) {
    asm volatile("ldmatrix.sync.aligned.m8n8.x4.trans.shared.b16 {%0,%1,%2,%3}, [%4];"
        : "=r"(r[0]), "=r"(r[1]), "=r"(r[2]), "=r"(r[3]) : "r"(a));
}
__device__ __forceinline__ void mma16816(float* c, const uint32_t* a, uint32_t b0, uint32_t b1) {
    asm volatile("mma.sync.aligned.m16n8k16.row.col.f32.f16.f16.f32 "
        "{%0,%1,%2,%3}, {%4,%5,%6,%7}, {%8,%9}, {%0,%1,%2,%3};"
        : "+f"(c[0]), "+f"(c[1]), "+f"(c[2]), "+f"(c[3])
        : "r"(a[0]), "r"(a[1]), "r"(a[2]), "r"(a[3]), "r"(b0), "r"(b1));
}
__device__ __forceinline__ void sts64(uint32_t addr, uint32_t a, uint32_t b) {
    asm volatile("st.shared.v2.b32 [%0], {%1,%2};" :: "r"(addr), "r"(a), "r"(b) : "memory");
}
__device__ __forceinline__ void sts128(uint32_t addr, uint4 v) {
    asm volatile("st.shared.v4.b32 [%0], {%1,%2,%3,%4};"
        :: "r"(addr), "r"(v.x), "r"(v.y), "r"(v.z), "r"(v.w) : "memory");
}
__device__ __forceinline__ void barg(int id) {
    asm volatile("bar.sync %0, %1;" :: "r"(id), "r"(128) : "memory");
}
__device__ __forceinline__ uint32_t h2(float a, float b) {
    __half2 h = __floats2half2_rn(a, b);
    return *(uint32_t*)&h;
}

// ---------------- kernel 0: w -> wT fp16 ----------------
__global__ __launch_bounds__(256) void prep_kernel(const float* __restrict__ w) {
    int e = blockIdx.x * 256 + threadIdx.x;
    int k = e >> 9, d = e & 511;
    g_wT[(size_t)k * D_ + d] = __float2half(w[(size_t)d * K_ + k]);
}

// ---------------- kernel 1: s = x@w (fp16 HMMA) + softmax -> aT  (R4, proven) ----
__global__ __launch_bounds__(256) void gemm1_kernel(const float* __restrict__ x) {
    __shared__ __align__(1024) char smem[49152];
    const uint32_t S0 = smem_u32(smem);
    float* stage = (float*)smem;                   // overlay post-loop: 128x66 f32

    const int t = threadIdx.x, wid = t >> 5, l = t & 31;
    const int bIdx = blockIdx.x >> 3, tile = blockIdx.x & 7;
    const float* xb = x + ((size_t)bIdx * N_ + (size_t)tile * 128) * D_;

    float acc[8][4];
#pragma unroll
    for (int f = 0; f < 8; f++)
#pragma unroll
        for (int j = 0; j < 4; j++) acc[f][j] = 0.f;

    const int rA  = (l & 15);
    const int cA8 = (l >> 4) << 3;
    const int rB  = (l & 7) + ((l >> 4) << 3);
    const int cB8 = ((l >> 3) & 1) << 3;

    float4 rx[8];
    uint4  rw[2];

    auto ldg_chunk = [&](int c) {
        const int d0 = c * 64;
#pragma unroll
        for (int i = 0; i < 8; i++) {
            int e = t + i * 256, r = e >> 4, f4 = e & 15;
            rx[i] = *(const float4*)(xb + (size_t)r * D_ + d0 + f4 * 4);
        }
#pragma unroll
        for (int i = 0; i < 2; i++) {
            int e = t + i * 256, r = e >> 3, u = e & 7;
            rw[i] = *(const uint4*)((const char*)g_wT + ((size_t)r * D_ + d0) * 2 + u * 16);
        }
    };
    auto sts_chunk = [&](int buf) {
        const uint32_t XH = S0 + buf * 24576, WH = XH + 16384;
#pragma unroll
        for (int i = 0; i < 8; i++) {
            int e = t + i * 256, r = e >> 4, f4 = e & 15;
            sts64(XH + sw128((uint32_t)(r * 128 + f4 * 8)),
                  h2(rx[i].x, rx[i].y), h2(rx[i].z, rx[i].w));
        }
#pragma unroll
        for (int i = 0; i < 2; i++) {
            int e = t + i * 256, r = e >> 3, u = e & 7;
            sts128(WH + sw128((uint32_t)(r * 128 + u * 16)), rw[i]);
        }
    };

    ldg_chunk(0);
    sts_chunk(0);
    __syncthreads();

#pragma unroll
    for (int c = 0; c < 8; c++) {
        if (c < 7) ldg_chunk(c + 1);
        const uint32_t XH = S0 + (c & 1) * 24576, WH = XH + 16384;
#pragma unroll
        for (int ks = 0; ks < 4; ks++) {
            const int k0 = ks * 16;
            uint32_t ah[4];
            ldsm_x4(ah, XH + sw128((uint32_t)((16 * wid + rA) * 128 + (k0 + cA8) * 2)));
#pragma unroll
            for (int fp = 0; fp < 4; fp++) {
                uint32_t bh[4];
                ldsm_x4(bh, WH + sw128((uint32_t)((fp * 16 + rB) * 128 + (k0 + cB8) * 2)));
                mma16816(acc[2*fp],   ah, bh[0], bh[1]);
                mma16816(acc[2*fp+1], ah, bh[2], bh[3]);
            }
        }
        if (c < 7) {
            sts_chunk((c + 1) & 1);
            __syncthreads();
        }
    }
    __syncthreads();

    // softmax (rows r0 = 16*wid + l/4 and r0+8)
    const int q = l >> 2, qq = l & 3;
    const int r0 = 16 * wid + q;
    float m0 = -1e30f, m1 = -1e30f;
#pragma unroll
    for (int f = 0; f < 8; f++) {
        m0 = fmaxf(m0, fmaxf(acc[f][0], acc[f][1]));
        m1 = fmaxf(m1, fmaxf(acc[f][2], acc[f][3]));
    }
    m0 = fmaxf(m0, __shfl_xor_sync(~0u, m0, 1));
    m0 = fmaxf(m0, __shfl_xor_sync(~0u, m0, 2));
    m1 = fmaxf(m1, __shfl_xor_sync(~0u, m1, 1));
    m1 = fmaxf(m1, __shfl_xor_sync(~0u, m1, 2));
    float s0 = 0.f, s1 = 0.f;
#pragma unroll
    for (int f = 0; f < 8; f++) {
        acc[f][0] = __expf(acc[f][0] - m0);
        acc[f][1] = __expf(acc[f][1] - m0);
        acc[f][2] = __expf(acc[f][2] - m1);
        acc[f][3] = __expf(acc[f][3] - m1);
        s0 += acc[f][0] + acc[f][1];
        s1 += acc[f][2] + acc[f][3];
    }
    s0 += __shfl_xor_sync(~0u, s0, 1); s0 += __shfl_xor_sync(~0u, s0, 2);
    s1 += __shfl_xor_sync(~0u, s1, 1); s1 += __shfl_xor_sync(~0u, s1, 2);
    const float i0 = 1.0f / s0, i1 = 1.0f / s1;
#pragma unroll
    for (int f = 0; f < 8; f++) {
        *(float2*)&stage[r0 * 66 + 8 * f + 2 * qq]       = make_float2(acc[f][0] * i0, acc[f][1] * i0);
        *(float2*)&stage[(r0 + 8) * 66 + 8 * f + 2 * qq] = make_float2(acc[f][2] * i1, acc[f][3] * i1);
    }
    __syncthreads();

    if (t < 64) {
        float s = 0.f;
#pragma unroll 8
        for (int r = 0; r < 128; r++) s += stage[r * 66 + t];
        g_asum_part[(bIdx * 8 + tile) * 64 + t] = s;
    }
    const size_t abase = (size_t)bIdx * K_ * N_ + (size_t)tile * 128;
    for (int e = t; e < 64 * 128; e += 256) {
        int k = e >> 7, j = e & 127;
        g_aT[abase + (size_t)k * N_ + j] = __float2half(stage[j * 66 + k]);
    }
}

// ---------------- kernel 2 (v2): vT[d,k] = sum_n x[n,d]*a[n,k] ----------------
// grid (8 d-tiles of 64, 64 b), 256 threads = two 4-warp n-groups.
// Group g buffers @ S0 + g*32768: XB0(8K) XB1(8K) AB0(8K) AB1(8K).
// Post-loop overlays: sredB @32768 (16KB), s_asum @49152, s_red2 @50176.
#define SMEM_G2 65536

__global__ __launch_bounds__(256) void gemm2_kernel(const float* __restrict__ x,
                                                    const float* __restrict__ Cm) {
    extern __shared__ __align__(1024) char smem[];
    const uint32_t S0 = smem_u32(smem);
    float* sredB  = (float*)(smem + 32768);
    float* s_asum = (float*)(smem + 49152);
    float* s_red2 = (float*)(smem + 50176);

    const int t = threadIdx.x, wid = t >> 5, l = t & 31;
    const int wg = t >> 7, wt = t & 127, w4 = wid & 3;
    const int bIdx = blockIdx.y, d0 = blockIdx.x * 64;
    const uint32_t G = S0 + (uint32_t)wg * 32768;

    const float* xb = x + (size_t)bIdx * N_ * D_ + d0;
    const __half* ath = g_aT + (size_t)bIdx * K_ * N_;
    const int nbase = wg * 512;

    float acc[8][4];
#pragma unroll
    for (int f = 0; f < 8; f++)
#pragma unroll
        for (int j = 0; j < 4; j++) acc[f][j] = 0.f;

    const int rT = (l & 7) + ((l >> 4) << 3);
    const int c8 = ((l >> 3) & 1) << 3;

    float4 rx[8];
    uint4  ra[4];

    auto ldg_chunk = [&](int cc) {
        const int n0 = nbase + cc * 64;
#pragma unroll
        for (int i = 0; i < 8; i++) {
            int e = wt + i * 128, r = e >> 4, f4 = e & 15;
            rx[i] = *(const float4*)(xb + (size_t)(n0 + r) * D_ + f4 * 4);
        }
#pragma unroll
        for (int i = 0; i < 4; i++) {
            int e = wt + i * 128, r = e >> 3, u = e & 7;
            ra[i] = *(const uint4*)((const char*)(ath + (size_t)r * N_ + n0) + u * 16);
        }
    };
    auto sts_chunk = [&](int buf) {
        const uint32_t XB = G + buf * 8192, AB = G + 16384 + buf * 8192;
#pragma unroll
        for (int i = 0; i < 8; i++) {
            int e = wt + i * 128, r = e >> 4, f4 = e & 15;
            sts64(XB + sw128((uint32_t)(r * 128 + f4 * 8)),
                  h2(rx[i].x, rx[i].y), h2(rx[i].z, rx[i].w));
        }
#pragma unroll
        for (int i = 0; i < 4; i++) {
            int e = wt + i * 128, r = e >> 3, u = e & 7;
            sts128(AB + sw128((uint32_t)(r * 128 + u * 16)), ra[i]);
        }
    };

    ldg_chunk(0);
    sts_chunk(0);
    barg(1 + wg);

#pragma unroll 1
    for (int cc = 0; cc < 8; cc++) {
        if (cc < 7) ldg_chunk(cc + 1);
        const uint32_t XB = G + (cc & 1) * 8192, AB = G + 16384 + (cc & 1) * 8192;
#pragma unroll
        for (int ns = 0; ns < 4; ns++) {
            const int nk = ns * 16;
            uint32_t ah[4];
            ldsm_x4t(ah, XB + sw128((uint32_t)((nk + rT) * 128 + (w4 * 16 + c8) * 2)));
#pragma unroll
            for (int fp = 0; fp < 4; fp++) {
                uint32_t bh[4];
                ldsm_x4(bh, AB + sw128((uint32_t)((fp * 16 + rT) * 128 + (nk + c8) * 2)));
                mma16816(acc[2*fp],   ah, bh[0], bh[1]);
                mma16816(acc[2*fp+1], ah, bh[2], bh[3]);
            }
        }
        if (cc < 7) {
            sts_chunk((cc + 1) & 1);
            barg(1 + wg);
        }
    }
    __syncthreads();   // both groups done computing

    const int q = l >> 2, qq = l & 3;
    // group B publishes partial acc; asum loaded
    if (wg == 1) {
        const int dg0 = 16 * w4 + q;
#pragma unroll
        for (int f = 0; f < 8; f++) {
            const int k0 = 8 * f + 2 * qq;
            *(float2*)&sredB[dg0 * 64 + k0]       = make_float2(acc[f][0], acc[f][1]);
            *(float2*)&sredB[(dg0 + 8) * 64 + k0] = make_float2(acc[f][2], acc[f][3]);
        }
    }
    if (t < 64) {
        float s = 0.f;
#pragma unroll
        for (int p = 0; p < 8; p++) s += g_asum_part[(bIdx * 8 + p) * 64 + t];
        s_asum[t] = s;
    }
    __syncthreads();

    if (wg == 0) {
        const int dg0 = 16 * w4 + q;
        float sq[8][2];
#pragma unroll
        for (int f = 0; f < 8; f++) {
            const int k0 = 8 * f + 2 * qq;
            float as0 = s_asum[k0], as1 = s_asum[k0 + 1];
            float2 r0 = *(const float2*)&sredB[dg0 * 64 + k0];
            float2 r1 = *(const float2*)&sredB[(dg0 + 8) * 64 + k0];
            float2 c0 = *(const float2*)(Cm + (size_t)(d0 + dg0) * K_ + k0);
            float2 c1 = *(const float2*)(Cm + (size_t)(d0 + dg0 + 8) * K_ + k0);
            float v00 = acc[f][0] + r0.x + as0 * c0.x;
            float v01 = acc[f][1] + r0.y + as1 * c0.y;
            float v10 = acc[f][2] + r1.x + as0 * c1.x;
            float v11 = acc[f][3] + r1.y + as1 * c1.y;
            *(float2*)(g_v + ((size_t)bIdx * D_ + d0 + dg0) * K_ + k0)     = make_float2(v00, v01);
            *(float2*)(g_v + ((size_t)bIdx * D_ + d0 + dg0 + 8) * K_ + k0) = make_float2(v10, v11);
            sq[f][0] = v00 * v00 + v10 * v10;
            sq[f][1] = v01 * v01 + v11 * v11;
        }
#pragma unroll
        for (int f = 0; f < 8; f++)
#pragma unroll
            for (int j = 0; j < 2; j++) {
                float v = sq[f][j];
                v += __shfl_xor_sync(~0u, v, 4);
                v += __shfl_xor_sync(~0u, v, 8);
                v += __shfl_xor_sync(~0u, v, 16);
                sq[f][j] = v;
            }
        if (l < 4) {
#pragma unroll
            for (int f = 0; f < 8; f++) {
                s_red2[w4 * 64 + 8 * f + 2 * l]     = sq[f][0];
                s_red2[w4 * 64 + 8 * f + 2 * l + 1] = sq[f][1];
            }
        }
    }
    __syncthreads();
    if (t < 64) {
        float S = s_red2[t] + s_red2[64 + t] + s_red2[128 + t] + s_red2[192 + t];
        g_S_part[(bIdx * 8 + blockIdx.x) * 64 + t] = S;
    }
}

// ---------------- kernel 3: fused norms + final scale ----------------
__global__ __launch_bounds__(256) void scale_kernel(float* __restrict__ out) {
    __shared__ float sS[64];
    __shared__ float sInv[64];
    __shared__ float sG;
    const int b = blockIdx.x >> 3, seg = blockIdx.x & 7, t = threadIdx.x;
    if (t < 64) {
        float s = 0.f;
#pragma unroll
        for (int p = 0; p < 8; p++) s += g_S_part[(b * 8 + p) * 64 + t];
        sS[t] = s;
        sInv[t] = rsqrtf(s + EPS_);
    }
    __syncthreads();
    if (t < 32) {
        float a0 = sS[t], a1 = sS[t + 32];
        float g = a0 / (a0 + EPS_) + a1 / (a1 + EPS_);
#pragma unroll
        for (int off = 16; off; off >>= 1) g += __shfl_xor_sync(~0u, g, off);
        if (t == 0) sG = rsqrtf(g + EPS_);
    }
    __syncthreads();
    const float gg = sG;
    const float4* vb = (const float4*)(g_v + (size_t)b * D_ * K_);
    float4* ob = (float4*)(out + (size_t)b * D_ * K_);
#pragma unroll
    for (int i = 0; i < 4; i++) {
        int e4 = seg * 1024 + t + i * 256;
        float4 v = vb[e4];
        int k = (e4 & 15) * 4;
        v.x *= sInv[k] * gg; v.y *= sInv[k + 1] * gg;
        v.z *= sInv[k + 2] * gg; v.w *= sInv[k + 3] * gg;
        ob[e4] = v;
    }
}

// ---------------------------------------------------------------------------
extern "C" void kernel_launch(void* const* d_in, const int* in_sizes, int n_in,
                              void* d_out, int out_size) {
    const float* x  = (const float*)d_in[0];   // [B,H,W,D]
    const float* w  = (const float*)d_in[1];   // [D,K]
    const float* Cm = (const float*)d_in[2];   // [D,K]
    float* out = (float*)d_out;                // [B, D*K]

    cudaFuncSetAttribute(gemm2_kernel, cudaFuncAttributeMaxDynamicSharedMemorySize, SMEM_G2);

    prep_kernel<<<128, 256>>>(w);
    gemm1_kernel<<<512, 256>>>(x);
    gemm2_kernel<<<dim3(8, B_), 256, SMEM_G2>>>(x, Cm);
    scale_kernel<<<512, 256>>>(out);
}